// round 15
// baseline (speedup 1.0000x reference)
#include <cuda_runtime.h>
#include <cuda_fp16.h>
#include <cstdint>

#define BATCH   2
#define SEQ     2048
#define DMODEL  1024
#define NHEADS  16
#define DHEAD   64
#define N3      3072
#define MROWS   (BATCH * SEQ)

// fp16 GEMM operands
__device__ __half g_xh[(size_t)MROWS * DMODEL];
__device__ __half g_wh[(size_t)N3 * DMODEL];          // W^T fp16 [n][k]
// qkv fp16 (all single), layout [b][h][s][dh]
#define QKV_ELEMS ((size_t)BATCH * NHEADS * SEQ * DHEAD)
__device__ __half g_qh[QKV_ELEMS];
__device__ __half g_kh[QKV_ELEMS];
__device__ __half g_vh[QKV_ELEMS];

typedef unsigned long long u64;

__device__ __forceinline__ uint32_t smem_u32(const void* p) {
    uint32_t a;
    asm("{ .reg .u64 t; cvta.to.shared.u64 t, %1; cvt.u32.u64 %0, t; }" : "=r"(a) : "l"(p));
    return a;
}
__device__ __forceinline__ void ldmx4(uint32_t* r, uint32_t addr) {
    asm volatile("ldmatrix.sync.aligned.m8n8.x4.shared.b16 {%0,%1,%2,%3}, [%4];"
        : "=r"(r[0]), "=r"(r[1]), "=r"(r[2]), "=r"(r[3]) : "r"(addr));
}
__device__ __forceinline__ void ldmx4t(uint32_t* r, uint32_t addr) {
    asm volatile("ldmatrix.sync.aligned.m8n8.x4.trans.shared.b16 {%0,%1,%2,%3}, [%4];"
        : "=r"(r[0]), "=r"(r[1]), "=r"(r[2]), "=r"(r[3]) : "r"(addr));
}
__device__ __forceinline__ void mma_f16(float* d, const uint32_t* a,
                                        uint32_t b0, uint32_t b1) {
    asm volatile("mma.sync.aligned.m16n8k16.row.col.f32.f16.f16.f32 "
        "{%0,%1,%2,%3}, {%4,%5,%6,%7}, {%8,%9}, {%0,%1,%2,%3};"
        : "+f"(d[0]), "+f"(d[1]), "+f"(d[2]), "+f"(d[3])
        : "r"(a[0]), "r"(a[1]), "r"(a[2]), "r"(a[3]), "r"(b0), "r"(b1));
}
__device__ __forceinline__ uint32_t cvt2h(float lo, float hi) {
    uint32_t r;
    asm("cvt.rn.f16x2.f32 %0, %1, %2;" : "=r"(r) : "f"(hi), "f"(lo));
    return r;
}
__device__ __forceinline__ float ex2(float x) {
    float r; asm("ex2.approx.ftz.f32 %0, %1;" : "=f"(r) : "f"(x)); return r;
}
__device__ __forceinline__ void cp16(uint32_t d, const void* g) {
    asm volatile("cp.async.cg.shared.global [%0], [%1], 16;" :: "r"(d), "l"(g) : "memory");
}
#define CP_COMMIT() asm volatile("cp.async.commit_group;" ::: "memory")
#define CP_WAIT0()  asm volatile("cp.async.wait_group 0;" ::: "memory")
#define CP_WAIT1()  asm volatile("cp.async.wait_group 1;" ::: "memory")
#define CP_WAIT2()  asm volatile("cp.async.wait_group 2;" ::: "memory")

// ---------------------------------------------------------------------------
// Fused conversion: blocks [0, XB) do x -> fp16; blocks [XB, XB+WB) do W^T.
// ---------------------------------------------------------------------------
#define XB (MROWS * DMODEL / 4 / 256)   // 4096
#define WB ((N3 / 32) * (DMODEL / 32))  // 3072

__global__ __launch_bounds__(256) void conv_fused(const float* __restrict__ x,
                                                  const float* __restrict__ W) {
    const int t = threadIdx.x;
    if (blockIdx.x < XB) {
        int i = blockIdx.x * 256 + t;
        float4 v = ((const float4*)x)[i];
        ((uint32_t*)g_xh)[2 * i + 0] = cvt2h(v.x, v.y);
        ((uint32_t*)g_xh)[2 * i + 1] = cvt2h(v.z, v.w);
    } else {
        __shared__ float tl[32][33];
        const int bx = blockIdx.x - XB;
        const int tx = t & 31, ty = t >> 5;             // 32 x 8
        const int n0 = (bx % (N3 / 32)) * 32;
        const int k0 = (bx / (N3 / 32)) * 32;
#pragma unroll
        for (int j = 0; j < 4; j++)
            tl[ty + j * 8][tx] = W[(size_t)(k0 + ty + j * 8) * N3 + n0 + tx];
        __syncthreads();
#pragma unroll
        for (int j = 0; j < 4; j++) {
            int n = n0 + ty + j * 8, k = k0 + tx;
            g_wh[(size_t)n * DMODEL + k] = __float2half_rn(tl[tx][ty + j * 8]);
        }
    }
}

// ---------------------------------------------------------------------------
// fp16 1-term QKV GEMM, 4-stage cp.async pipeline, ONE sync per chunk.
// (unchanged from R14)
// ---------------------------------------------------------------------------
#define PITCH 80
#define GB (2 * 128 * PITCH)        // 20480 per stage
#define GEMM_SMEM (4 * GB)          // 81920

__global__ __launch_bounds__(256, 2) void gemm_mma(const float* __restrict__ bias) {
    extern __shared__ char smem[];

    const int t   = threadIdx.x;
    const int wid = t >> 5, lid = t & 31;
    const int n0  = blockIdx.x * 128;
    const int m0  = blockIdx.y * 128;
    const int wm  = wid >> 2;
    const int wn  = wid & 3;

    const uint32_t sb = smem_u32(smem);
    const int sub = lid >> 3, r8 = lid & 7;
    const uint32_t lane_off =
        (uint32_t)((r8 + ((sub & 1) << 3)) * PITCH + ((sub >> 1) << 4));

    const __half* gp[4];
    uint32_t sp[4];
#pragma unroll
    for (int it = 0; it < 4; it++) {
        int idx = t + it * 256;
        int mat = idx >> 9, w = idx & 511;
        int row = w >> 2, c16 = w & 3;
        const __half* base;
        int grow;
        if (mat == 0) { base = g_xh; grow = m0 + row; }
        else          { base = g_wh; grow = n0 + row; }
        gp[it] = base + (size_t)grow * DMODEL + c16 * 8;
        sp[it] = sb + (uint32_t)(mat * 128 * PITCH + row * PITCH + c16 * 16);
    }

#pragma unroll
    for (int s = 0; s < 3; s++) {
#pragma unroll
        for (int it = 0; it < 4; it++) cp16(sp[it] + s * GB, gp[it] + s * 32);
        CP_COMMIT();
    }

    float acc[4][4][4] = {};
    const int NCH = DMODEL / 32;   // 32

    for (int ch = 0; ch < NCH; ch++) {
        if (ch >= NCH - 1)      { CP_WAIT0(); }
        else if (ch >= NCH - 2) { CP_WAIT1(); }
        else                    { CP_WAIT2(); }
        __syncthreads();
        const uint32_t bo = (uint32_t)((ch & 3) * GB);
        const uint32_t sAXH = sb + bo;
        const uint32_t sBWH = sAXH + 128 * PITCH;

#pragma unroll
        for (int ks = 0; ks < 2; ks++) {
            const uint32_t kso = ks * 32;
            uint32_t bw[2][4];
#pragma unroll
            for (int np = 0; np < 2; np++) {
                uint32_t baddr = (uint32_t)((wn * 32 + np * 16) * PITCH) + kso + lane_off;
                ldmx4(bw[np], sBWH + baddr);
            }
#pragma unroll
            for (int mt = 0; mt < 4; mt++) {
                uint32_t aaddr = (uint32_t)((wm * 64 + mt * 16) * PITCH) + kso + lane_off;
                uint32_t ah[4];
                ldmx4(ah, sAXH + aaddr);
#pragma unroll
                for (int nt = 0; nt < 4; nt++) {
                    const int np = nt >> 1, o = nt & 1;
                    mma_f16(acc[mt][nt], ah, bw[np][o], bw[np][2 + o]);
                }
            }
        }
        if (ch + 3 < NCH) {
            const int ko = (ch + 3) * 32;
            const uint32_t wo = (uint32_t)(((ch + 3) & 3) * GB);
#pragma unroll
            for (int it = 0; it < 4; it++) cp16(sp[it] + wo, gp[it] + ko);
            CP_COMMIT();
        }
    }

    const int gid = lid >> 2, tg = lid & 3;
    const int part = n0 >> 10;
    __half* p_ = (part == 0) ? g_qh : (part == 1) ? g_kh : g_vh;

#pragma unroll
    for (int nt = 0; nt < 4; nt++) {
        const int col = n0 + wn * 32 + nt * 8 + tg * 2;
        const float2 bv = *(const float2*)&bias[col];
        const int h = (col >> 6) & 15, dh0 = col & 63;
#pragma unroll
        for (int mt = 0; mt < 4; mt++) {
            const int row0 = m0 + wm * 64 + mt * 16 + gid;
#pragma unroll
            for (int half = 0; half < 2; half++) {
                const int row = row0 + half * 8;
                const int bb = row >> 11, s = row & 2047;
                const size_t idx =
                    ((size_t)(bb * NHEADS + h) * SEQ + s) * DHEAD + dh0;
                *(uint32_t*)(p_ + idx) =
                    cvt2h(acc[mt][nt][2 * half + 0] + bv.x,
                          acc[mt][nt][2 * half + 1] + bv.y);
            }
        }
    }
}

// ---------------------------------------------------------------------------
// fp16 flash attention v2: Q hoisted to registers, 128-key KV tiles,
// 3 buffers, ONE sync per 128 keys (16 iterations).
// Each 128-key tile processed in two 64-key halves (reg pressure unchanged).
// smem: 3 x [K 128 rows | V 128 rows], pitch 144. Q stages through buf0.
// ---------------------------------------------------------------------------
#define AP 144
#define KVSZ (2 * 128 * AP)             // 36864: K 0..18432 | V 18432..36864
#define VOFF (128 * AP)                 // 18432
#define ATTN_SMEM (3 * KVSZ)            // 110592

__global__ __launch_bounds__(256, 2) void attn_mma(float* __restrict__ out) {
    extern __shared__ char sm[];
    const uint32_t sb = smem_u32(sm);
    const int t = threadIdx.x, w = t >> 5, lid = t & 31;
    const int gid = lid >> 2, tg = lid & 3;
    const int sub = lid >> 3, r8 = lid & 7;
    const uint32_t lane_off =
        (uint32_t)((r8 + ((sub & 1) << 3)) * AP + ((sub >> 1) << 4));

    const int q0 = blockIdx.x * 128;
    const int h  = blockIdx.y;
    const int bb = blockIdx.z;
    const size_t base = (size_t)(bb * NHEADS + h) * SEQ * DHEAD;

    const int row = t >> 3, c16 = t & 7;   // row 0..31, c16 0..7

    // issue a 128-key KV tile into buffer kvb_: thread covers rows row+32i
#define ISSUE_KV(k0_, kvb_) do {                                               \
        size_t g_ = base + (size_t)((k0_) + row) * DHEAD + c16 * 8;            \
        uint32_t d_ = sb + (uint32_t)(kvb_) + (uint32_t)(row * AP + c16 * 16); \
        _Pragma("unroll")                                                      \
        for (int ii = 0; ii < 4; ii++) {                                       \
            cp16(d_ + 0,    g_kh + g_);                                        \
            cp16(d_ + VOFF, g_vh + g_);                                        \
            g_ += 32 * DHEAD; d_ += 32 * AP;                                   \
        }                                                                      \
    } while (0)

    // ---- stage Q through buffer 0, load Q fragments, then start pipeline --
#pragma unroll
    for (int i = 0; i < 4; i++) {
        const int qr = row + 32 * i;
        const size_t g = base + (size_t)(q0 + qr) * DHEAD + c16 * 8;
        cp16(sb + (uint32_t)(qr * AP + c16 * 16), g_qh + g);
    }
    CP_COMMIT();
    CP_WAIT0();
    __syncthreads();

    uint32_t qf[4][4];
#pragma unroll
    for (int kc = 0; kc < 4; kc++)
        ldmx4(qf[kc], sb + (uint32_t)(w * 16 * AP) + kc * 32 + lane_off);
    __syncthreads();   // all warps hold Q in regs; buffer 0 reusable

    ISSUE_KV(0, 0);
    CP_COMMIT();
    ISSUE_KV(128, KVSZ);
    CP_COMMIT();

    float oacc[8][4] = {};
    float l0 = 0.f, l1 = 0.f;
    const float SL2E = 0.125f * 1.4426950408889634f;
    const float NCM  = -6.0f * 1.4426950408889634f;

    const int NT = SEQ / 128;   // 16
    int cur = 0;                // kt % 3
    for (int kt = 0; kt < NT; kt++) {
        if (kt == NT - 1) { CP_WAIT0(); } else { CP_WAIT1(); }
        __syncthreads();
        const uint32_t kvb = sb + (uint32_t)(cur * KVSZ);

#pragma unroll
        for (int half = 0; half < 2; half++) {
            const uint32_t kbase = kvb + (uint32_t)(half * 64 * AP);
            const uint32_t vbase = kvb + VOFF + (uint32_t)(half * 64 * AP);

            // ---- S = Q K^T (64 keys) ----
            float sacc[8][4] = {};
#pragma unroll
            for (int kc = 0; kc < 4; kc++) {
#pragma unroll
                for (int np = 0; np < 4; np++) {
                    uint32_t kh4[4];
                    ldmx4(kh4, kbase + (uint32_t)(np * 16 * AP) + kc * 32 + lane_off);
#pragma unroll
                    for (int o = 0; o < 2; o++)
                        mma_f16(sacc[2 * np + o], qf[kc], kh4[o], kh4[2 + o]);
                }
            }

            // ---- fused softmax + PV ----
#pragma unroll
            for (int kc = 0; kc < 4; kc++) {
                const int j0 = 2 * kc, j1 = 2 * kc + 1;
                sacc[j0][0] = ex2(fmaf(sacc[j0][0], SL2E, NCM));
                sacc[j0][1] = ex2(fmaf(sacc[j0][1], SL2E, NCM));
                sacc[j0][2] = ex2(fmaf(sacc[j0][2], SL2E, NCM));
                sacc[j0][3] = ex2(fmaf(sacc[j0][3], SL2E, NCM));
                sacc[j1][0] = ex2(fmaf(sacc[j1][0], SL2E, NCM));
                sacc[j1][1] = ex2(fmaf(sacc[j1][1], SL2E, NCM));
                sacc[j1][2] = ex2(fmaf(sacc[j1][2], SL2E, NCM));
                sacc[j1][3] = ex2(fmaf(sacc[j1][3], SL2E, NCM));
                l0 += sacc[j0][0] + sacc[j0][1] + sacc[j1][0] + sacc[j1][1];
                l1 += sacc[j0][2] + sacc[j0][3] + sacc[j1][2] + sacc[j1][3];
                uint32_t pah[4];
                pah[0] = cvt2h(sacc[j0][0], sacc[j0][1]);
                pah[1] = cvt2h(sacc[j0][2], sacc[j0][3]);
                pah[2] = cvt2h(sacc[j1][0], sacc[j1][1]);
                pah[3] = cvt2h(sacc[j1][2], sacc[j1][3]);
#pragma unroll
                for (int np = 0; np < 4; np++) {
                    uint32_t vh4[4];
                    ldmx4t(vh4, vbase + (uint32_t)((kc * 16) * AP) + np * 32 + lane_off);
#pragma unroll
                    for (int o = 0; o < 2; o++)
                        mma_f16(oacc[2 * np + o], pah, vh4[2 * o], vh4[2 * o + 1]);
                }
            }
        }

        // no tail sync: write target (kt+2)%3 == (kt-1)%3, consumed at kt-1
        if (kt + 2 < NT) {
            const int nb = (cur + 2 >= 3) ? cur - 1 : cur + 2;
            ISSUE_KV((kt + 2) * 128, nb * KVSZ);
            CP_COMMIT();
        }
        cur = (cur == 2) ? 0 : cur + 1;
    }

    // ---- final row-sum reduction, normalize, write ----
    l0 += __shfl_xor_sync(0xffffffffu, l0, 1);
    l0 += __shfl_xor_sync(0xffffffffu, l0, 2);
    l1 += __shfl_xor_sync(0xffffffffu, l1, 1);
    l1 += __shfl_xor_sync(0xffffffffu, l1, 2);
    const float inv0 = 1.0f / l0, inv1 = 1.0f / l1;
    const int qa = q0 + w * 16 + gid;
    const int qb = qa + 8;
#pragma unroll
    for (int j = 0; j < 8; j++) {
        const int col = h * DHEAD + 8 * j + 2 * tg;
        float2 v0 = {oacc[j][0] * inv0, oacc[j][1] * inv0};
        float2 v1 = {oacc[j][2] * inv1, oacc[j][3] * inv1};
        *(float2*)(out + ((size_t)bb * SEQ + qa) * DMODEL + col) = v0;
        *(float2*)(out + ((size_t)bb * SEQ + qb) * DMODEL + col) = v1;
    }
}

extern "C" void kernel_launch(void* const* d_in, const int* in_sizes, int n_in,
                              void* d_out, int out_size) {
    const float* x    = (const float*)d_in[0];
    const float* W    = (const float*)d_in[1];
    const float* bias = (const float*)d_in[2];
    float* out = (float*)d_out;

    conv_fused<<<XB + WB, 256>>>(x, W);

    (void)cudaFuncSetAttribute(gemm_mma,
                               cudaFuncAttributeMaxDynamicSharedMemorySize, GEMM_SMEM);
    gemm_mma<<<dim3(N3 / 128, MROWS / 128), 256, GEMM_SMEM>>>(bias);

    (void)cudaFuncSetAttribute(attn_mma,
                               cudaFuncAttributeMaxDynamicSharedMemorySize, ATTN_SMEM);
    dim3 agrid(SEQ / 128, NHEADS, BATCH);
    attn_mma<<<agrid, 256, ATTN_SMEM>>>(out);
}

// round 16
// speedup vs baseline: 1.0397x; 1.0397x over previous
#include <cuda_runtime.h>
#include <cuda_fp16.h>
#include <cstdint>

#define BATCH   2
#define SEQ     2048
#define DMODEL  1024
#define NHEADS  16
#define DHEAD   64
#define N3      3072
#define MROWS   (BATCH * SEQ)

// fp16 GEMM operands
__device__ __half g_xh[(size_t)MROWS * DMODEL];
__device__ __half g_wh[(size_t)N3 * DMODEL];          // W^T fp16 [n][k]
// qkv fp16 (all single), layout [b][h][s][dh]
#define QKV_ELEMS ((size_t)BATCH * NHEADS * SEQ * DHEAD)
__device__ __half g_qh[QKV_ELEMS];
__device__ __half g_kh[QKV_ELEMS];
__device__ __half g_vh[QKV_ELEMS];

typedef unsigned long long u64;

__device__ __forceinline__ uint32_t smem_u32(const void* p) {
    uint32_t a;
    asm("{ .reg .u64 t; cvta.to.shared.u64 t, %1; cvt.u32.u64 %0, t; }" : "=r"(a) : "l"(p));
    return a;
}
__device__ __forceinline__ void ldmx4(uint32_t* r, uint32_t addr) {
    asm volatile("ldmatrix.sync.aligned.m8n8.x4.shared.b16 {%0,%1,%2,%3}, [%4];"
        : "=r"(r[0]), "=r"(r[1]), "=r"(r[2]), "=r"(r[3]) : "r"(addr));
}
__device__ __forceinline__ void ldmx4t(uint32_t* r, uint32_t addr) {
    asm volatile("ldmatrix.sync.aligned.m8n8.x4.trans.shared.b16 {%0,%1,%2,%3}, [%4];"
        : "=r"(r[0]), "=r"(r[1]), "=r"(r[2]), "=r"(r[3]) : "r"(addr));
}
__device__ __forceinline__ void mma_f16(float* d, const uint32_t* a,
                                        uint32_t b0, uint32_t b1) {
    asm volatile("mma.sync.aligned.m16n8k16.row.col.f32.f16.f16.f32 "
        "{%0,%1,%2,%3}, {%4,%5,%6,%7}, {%8,%9}, {%0,%1,%2,%3};"
        : "+f"(d[0]), "+f"(d[1]), "+f"(d[2]), "+f"(d[3])
        : "r"(a[0]), "r"(a[1]), "r"(a[2]), "r"(a[3]), "r"(b0), "r"(b1));
}
__device__ __forceinline__ uint32_t cvt2h(float lo, float hi) {
    uint32_t r;
    asm("cvt.rn.f16x2.f32 %0, %1, %2;" : "=r"(r) : "f"(hi), "f"(lo));
    return r;
}
__device__ __forceinline__ float ex2(float x) {
    float r; asm("ex2.approx.ftz.f32 %0, %1;" : "=f"(r) : "f"(x)); return r;
}
__device__ __forceinline__ void cp16(uint32_t d, const void* g) {
    asm volatile("cp.async.cg.shared.global [%0], [%1], 16;" :: "r"(d), "l"(g) : "memory");
}
#define CP_COMMIT() asm volatile("cp.async.commit_group;" ::: "memory")
#define CP_WAIT0()  asm volatile("cp.async.wait_group 0;" ::: "memory")
#define CP_WAIT1()  asm volatile("cp.async.wait_group 1;" ::: "memory")

// ---------------------------------------------------------------------------
// Fused conversion: blocks [0, XB) do x -> fp16; blocks [XB, XB+WB) do W^T.
// ---------------------------------------------------------------------------
#define XB (MROWS * DMODEL / 4 / 256)   // 4096
#define WB ((N3 / 32) * (DMODEL / 32))  // 3072

__global__ __launch_bounds__(256) void conv_fused(const float* __restrict__ x,
                                                  const float* __restrict__ W) {
    const int t = threadIdx.x;
    if (blockIdx.x < XB) {
        int i = blockIdx.x * 256 + t;
        float4 v = ((const float4*)x)[i];
        ((uint32_t*)g_xh)[2 * i + 0] = cvt2h(v.x, v.y);
        ((uint32_t*)g_xh)[2 * i + 1] = cvt2h(v.z, v.w);
    } else {
        __shared__ float tl[32][33];
        const int bx = blockIdx.x - XB;
        const int tx = t & 31, ty = t >> 5;             // 32 x 8
        const int n0 = (bx % (N3 / 32)) * 32;
        const int k0 = (bx / (N3 / 32)) * 32;
#pragma unroll
        for (int j = 0; j < 4; j++)
            tl[ty + j * 8][tx] = W[(size_t)(k0 + ty + j * 8) * N3 + n0 + tx];
        __syncthreads();
#pragma unroll
        for (int j = 0; j < 4; j++) {
            int n = n0 + ty + j * 8, k = k0 + tx;
            g_wh[(size_t)n * DMODEL + k] = __float2half_rn(tl[tx][ty + j * 8]);
        }
    }
}

// ---------------------------------------------------------------------------
// fp16 1-term QKV GEMM: K-chunk 64, 3 buffers, prefetch +2, ONE sync/chunk.
// Stage: A 128 rows | B 128 rows, pitch 144 (128B data + 16B pad). 110.6 KB.
// ---------------------------------------------------------------------------
#define GP 144
#define GSTG (2 * 128 * GP)         // 36864 per stage
#define GBOFF (128 * GP)            // B offset within stage
#define GEMM_SMEM (3 * GSTG)        // 110592

__global__ __launch_bounds__(256, 2) void gemm_mma(const float* __restrict__ bias) {
    extern __shared__ char smem[];

    const int t   = threadIdx.x;
    const int wid = t >> 5, lid = t & 31;
    const int n0  = blockIdx.x * 128;
    const int m0  = blockIdx.y * 128;
    const int wm  = wid >> 2;
    const int wn  = wid & 3;

    const uint32_t sb = smem_u32(smem);
    const int sub = lid >> 3, r8 = lid & 7;
    const uint32_t lane_off =
        (uint32_t)((r8 + ((sub & 1) << 3)) * GP + ((sub >> 1) << 4));

    // per chunk: 2 matrices x 128 rows x 8 16B-cols = 2048 slots / 256 = 8 each
    const __half* gp_[8];
    uint32_t sp_[8];
#pragma unroll
    for (int it = 0; it < 8; it++) {
        int idx = t + it * 256;
        int mat = idx >> 10, w = idx & 1023;
        int row = w >> 3, c16 = w & 7;
        const __half* base;
        int grow;
        if (mat == 0) { base = g_xh; grow = m0 + row; }
        else          { base = g_wh; grow = n0 + row; }
        gp_[it] = base + (size_t)grow * DMODEL + c16 * 8;
        sp_[it] = sb + (uint32_t)(mat * GBOFF + row * GP + c16 * 16);
    }

    // prologue: chunks 0,1 -> stages 0,1
#pragma unroll
    for (int s = 0; s < 2; s++) {
#pragma unroll
        for (int it = 0; it < 8; it++) cp16(sp_[it] + s * GSTG, gp_[it] + s * 64);
        CP_COMMIT();
    }

    float acc[4][4][4] = {};
    const int NCH = DMODEL / 64;   // 16
    int cur = 0;                   // ch % 3

    for (int ch = 0; ch < NCH; ch++) {
        if (ch == NCH - 1) { CP_WAIT0(); } else { CP_WAIT1(); }
        __syncthreads();
        const uint32_t sA = sb + (uint32_t)(cur * GSTG);
        const uint32_t sB = sA + GBOFF;

#pragma unroll
        for (int ks = 0; ks < 4; ks++) {
            const uint32_t kso = ks * 32;
            uint32_t bw[2][4];
#pragma unroll
            for (int np = 0; np < 2; np++) {
                uint32_t baddr = (uint32_t)((wn * 32 + np * 16) * GP) + kso + lane_off;
                ldmx4(bw[np], sB + baddr);
            }
#pragma unroll
            for (int mt = 0; mt < 4; mt++) {
                uint32_t aaddr = (uint32_t)((wm * 64 + mt * 16) * GP) + kso + lane_off;
                uint32_t ah[4];
                ldmx4(ah, sA + aaddr);
#pragma unroll
                for (int nt = 0; nt < 4; nt++) {
                    const int np = nt >> 1, o = nt & 1;
                    mma_f16(acc[mt][nt], ah, bw[np][o], bw[np][2 + o]);
                }
            }
        }
        // no tail sync: write chunk ch+2 into stage (ch+2)%3 == (ch-1)%3
        if (ch + 2 < NCH) {
            const int ko = (ch + 2) * 64;
            const int nb = (cur + 2 >= 3) ? cur - 1 : cur + 2;
            const uint32_t wo = (uint32_t)(nb * GSTG);
#pragma unroll
            for (int it = 0; it < 8; it++) cp16(sp_[it] + wo, gp_[it] + ko);
            CP_COMMIT();
        }
        cur = (cur == 2) ? 0 : cur + 1;
    }

    // epilogue: +bias; Q,K,V all single fp16
    const int gid = lid >> 2, tg = lid & 3;
    const int part = n0 >> 10;
    __half* p_ = (part == 0) ? g_qh : (part == 1) ? g_kh : g_vh;

#pragma unroll
    for (int nt = 0; nt < 4; nt++) {
        const int col = n0 + wn * 32 + nt * 8 + tg * 2;
        const float2 bv = *(const float2*)&bias[col];
        const int h = (col >> 6) & 15, dh0 = col & 63;
#pragma unroll
        for (int mt = 0; mt < 4; mt++) {
            const int row0 = m0 + wm * 64 + mt * 16 + gid;
#pragma unroll
            for (int half = 0; half < 2; half++) {
                const int row = row0 + half * 8;
                const int bb = row >> 11, s = row & 2047;
                const size_t idx =
                    ((size_t)(bb * NHEADS + h) * SEQ + s) * DHEAD + dh0;
                *(uint32_t*)(p_ + idx) =
                    cvt2h(acc[mt][nt][2 * half + 0] + bv.x,
                          acc[mt][nt][2 * half + 1] + bv.y);
            }
        }
    }
}

// ---------------------------------------------------------------------------
// fp16 flash attention (R15, unchanged): Q in registers, 128-key KV tiles,
// 3 buffers, ONE sync per tile.
// ---------------------------------------------------------------------------
#define AP 144
#define KVSZ (2 * 128 * AP)             // 36864: K | V
#define VOFF (128 * AP)                 // 18432
#define ATTN_SMEM (3 * KVSZ)            // 110592

__global__ __launch_bounds__(256, 2) void attn_mma(float* __restrict__ out) {
    extern __shared__ char sm[];
    const uint32_t sb = smem_u32(sm);
    const int t = threadIdx.x, w = t >> 5, lid = t & 31;
    const int gid = lid >> 2, tg = lid & 3;
    const int sub = lid >> 3, r8 = lid & 7;
    const uint32_t lane_off =
        (uint32_t)((r8 + ((sub & 1) << 3)) * AP + ((sub >> 1) << 4));

    const int q0 = blockIdx.x * 128;
    const int h  = blockIdx.y;
    const int bb = blockIdx.z;
    const size_t base = (size_t)(bb * NHEADS + h) * SEQ * DHEAD;

    const int row = t >> 3, c16 = t & 7;

#define ISSUE_KV(k0_, kvb_) do {                                               \
        size_t g_ = base + (size_t)((k0_) + row) * DHEAD + c16 * 8;            \
        uint32_t d_ = sb + (uint32_t)(kvb_) + (uint32_t)(row * AP + c16 * 16); \
        _Pragma("unroll")                                                      \
        for (int ii = 0; ii < 4; ii++) {                                       \
            cp16(d_ + 0,    g_kh + g_);                                        \
            cp16(d_ + VOFF, g_vh + g_);                                        \
            g_ += 32 * DHEAD; d_ += 32 * AP;                                   \
        }                                                                      \
    } while (0)

#pragma unroll
    for (int i = 0; i < 4; i++) {
        const int qr = row + 32 * i;
        const size_t g = base + (size_t)(q0 + qr) * DHEAD + c16 * 8;
        cp16(sb + (uint32_t)(qr * AP + c16 * 16), g_qh + g);
    }
    CP_COMMIT();
    CP_WAIT0();
    __syncthreads();

    uint32_t qf[4][4];
#pragma unroll
    for (int kc = 0; kc < 4; kc++)
        ldmx4(qf[kc], sb + (uint32_t)(w * 16 * AP) + kc * 32 + lane_off);
    __syncthreads();

    ISSUE_KV(0, 0);
    CP_COMMIT();
    ISSUE_KV(128, KVSZ);
    CP_COMMIT();

    float oacc[8][4] = {};
    float l0 = 0.f, l1 = 0.f;
    const float SL2E = 0.125f * 1.4426950408889634f;
    const float NCM  = -6.0f * 1.4426950408889634f;

    const int NT = SEQ / 128;   // 16
    int cur = 0;
    for (int kt = 0; kt < NT; kt++) {
        if (kt == NT - 1) { CP_WAIT0(); } else { CP_WAIT1(); }
        __syncthreads();
        const uint32_t kvb = sb + (uint32_t)(cur * KVSZ);

#pragma unroll
        for (int half = 0; half < 2; half++) {
            const uint32_t kbase = kvb + (uint32_t)(half * 64 * AP);
            const uint32_t vbase = kvb + VOFF + (uint32_t)(half * 64 * AP);

            float sacc[8][4] = {};
#pragma unroll
            for (int kc = 0; kc < 4; kc++) {
#pragma unroll
                for (int np = 0; np < 4; np++) {
                    uint32_t kh4[4];
                    ldmx4(kh4, kbase + (uint32_t)(np * 16 * AP) + kc * 32 + lane_off);
#pragma unroll
                    for (int o = 0; o < 2; o++)
                        mma_f16(sacc[2 * np + o], qf[kc], kh4[o], kh4[2 + o]);
                }
            }

#pragma unroll
            for (int kc = 0; kc < 4; kc++) {
                const int j0 = 2 * kc, j1 = 2 * kc + 1;
                sacc[j0][0] = ex2(fmaf(sacc[j0][0], SL2E, NCM));
                sacc[j0][1] = ex2(fmaf(sacc[j0][1], SL2E, NCM));
                sacc[j0][2] = ex2(fmaf(sacc[j0][2], SL2E, NCM));
                sacc[j0][3] = ex2(fmaf(sacc[j0][3], SL2E, NCM));
                sacc[j1][0] = ex2(fmaf(sacc[j1][0], SL2E, NCM));
                sacc[j1][1] = ex2(fmaf(sacc[j1][1], SL2E, NCM));
                sacc[j1][2] = ex2(fmaf(sacc[j1][2], SL2E, NCM));
                sacc[j1][3] = ex2(fmaf(sacc[j1][3], SL2E, NCM));
                l0 += sacc[j0][0] + sacc[j0][1] + sacc[j1][0] + sacc[j1][1];
                l1 += sacc[j0][2] + sacc[j0][3] + sacc[j1][2] + sacc[j1][3];
                uint32_t pah[4];
                pah[0] = cvt2h(sacc[j0][0], sacc[j0][1]);
                pah[1] = cvt2h(sacc[j0][2], sacc[j0][3]);
                pah[2] = cvt2h(sacc[j1][0], sacc[j1][1]);
                pah[3] = cvt2h(sacc[j1][2], sacc[j1][3]);
#pragma unroll
                for (int np = 0; np < 4; np++) {
                    uint32_t vh4[4];
                    ldmx4t(vh4, vbase + (uint32_t)((kc * 16) * AP) + np * 32 + lane_off);
#pragma unroll
                    for (int o = 0; o < 2; o++)
                        mma_f16(oacc[2 * np + o], pah, vh4[2 * o], vh4[2 * o + 1]);
                }
            }
        }

        if (kt + 2 < NT) {
            const int nb = (cur + 2 >= 3) ? cur - 1 : cur + 2;
            ISSUE_KV((kt + 2) * 128, nb * KVSZ);
            CP_COMMIT();
        }
        cur = (cur == 2) ? 0 : cur + 1;
    }

    l0 += __shfl_xor_sync(0xffffffffu, l0, 1);
    l0 += __shfl_xor_sync(0xffffffffu, l0, 2);
    l1 += __shfl_xor_sync(0xffffffffu, l1, 1);
    l1 += __shfl_xor_sync(0xffffffffu, l1, 2);
    const float inv0 = 1.0f / l0, inv1 = 1.0f / l1;
    const int qa = q0 + w * 16 + gid;
    const int qb = qa + 8;
#pragma unroll
    for (int j = 0; j < 8; j++) {
        const int col = h * DHEAD + 8 * j + 2 * tg;
        float2 v0 = {oacc[j][0] * inv0, oacc[j][1] * inv0};
        float2 v1 = {oacc[j][2] * inv1, oacc[j][3] * inv1};
        *(float2*)(out + ((size_t)bb * SEQ + qa) * DMODEL + col) = v0;
        *(float2*)(out + ((size_t)bb * SEQ + qb) * DMODEL + col) = v1;
    }
}

extern "C" void kernel_launch(void* const* d_in, const int* in_sizes, int n_in,
                              void* d_out, int out_size) {
    const float* x    = (const float*)d_in[0];
    const float* W    = (const float*)d_in[1];
    const float* bias = (const float*)d_in[2];
    float* out = (float*)d_out;

    conv_fused<<<XB + WB, 256>>>(x, W);

    (void)cudaFuncSetAttribute(gemm_mma,
                               cudaFuncAttributeMaxDynamicSharedMemorySize, GEMM_SMEM);
    gemm_mma<<<dim3(N3 / 128, MROWS / 128), 256, GEMM_SMEM>>>(bias);

    (void)cudaFuncSetAttribute(attn_mma,
                               cudaFuncAttributeMaxDynamicSharedMemorySize, ATTN_SMEM);
    dim3 agrid(SEQ / 128, NHEADS, BATCH);
    attn_mma<<<agrid, 256, ATTN_SMEM>>>(out);
}

// round 17
// speedup vs baseline: 1.1501x; 1.1061x over previous
#include <cuda_runtime.h>
#include <cuda_fp16.h>
#include <cstdint>

#define BATCH   2
#define SEQ     2048
#define DMODEL  1024
#define NHEADS  16
#define DHEAD   64
#define N3      3072
#define MROWS   (BATCH * SEQ)

// fp16 GEMM operands
__device__ __half g_xh[(size_t)MROWS * DMODEL];
__device__ __half g_wh[(size_t)N3 * DMODEL];          // W^T fp16 [n][k]
// qkv fp16 (all single), layout [b][h][s][dh]
#define QKV_ELEMS ((size_t)BATCH * NHEADS * SEQ * DHEAD)
__device__ __half g_qh[QKV_ELEMS];
__device__ __half g_kh[QKV_ELEMS];
__device__ __half g_vh[QKV_ELEMS];
// per-head-pair completion counters (8 head pairs; 96 GEMM blocks each)
__device__ unsigned int g_hp_cnt[8];

typedef unsigned long long u64;

__device__ __forceinline__ uint32_t smem_u32(const void* p) {
    uint32_t a;
    asm("{ .reg .u64 t; cvta.to.shared.u64 t, %1; cvt.u32.u64 %0, t; }" : "=r"(a) : "l"(p));
    return a;
}
__device__ __forceinline__ void ldmx4(uint32_t* r, uint32_t addr) {
    asm volatile("ldmatrix.sync.aligned.m8n8.x4.shared.b16 {%0,%1,%2,%3}, [%4];"
        : "=r"(r[0]), "=r"(r[1]), "=r"(r[2]), "=r"(r[3]) : "r"(addr));
}
__device__ __forceinline__ void ldmx4t(uint32_t* r, uint32_t addr) {
    asm volatile("ldmatrix.sync.aligned.m8n8.x4.trans.shared.b16 {%0,%1,%2,%3}, [%4];"
        : "=r"(r[0]), "=r"(r[1]), "=r"(r[2]), "=r"(r[3]) : "r"(addr));
}
__device__ __forceinline__ void mma_f16(float* d, const uint32_t* a,
                                        uint32_t b0, uint32_t b1) {
    asm volatile("mma.sync.aligned.m16n8k16.row.col.f32.f16.f16.f32 "
        "{%0,%1,%2,%3}, {%4,%5,%6,%7}, {%8,%9}, {%0,%1,%2,%3};"
        : "+f"(d[0]), "+f"(d[1]), "+f"(d[2]), "+f"(d[3])
        : "r"(a[0]), "r"(a[1]), "r"(a[2]), "r"(a[3]), "r"(b0), "r"(b1));
}
__device__ __forceinline__ uint32_t cvt2h(float lo, float hi) {
    uint32_t r;
    asm("cvt.rn.f16x2.f32 %0, %1, %2;" : "=r"(r) : "f"(hi), "f"(lo));
    return r;
}
__device__ __forceinline__ float ex2(float x) {
    float r; asm("ex2.approx.ftz.f32 %0, %1;" : "=f"(r) : "f"(x)); return r;
}
__device__ __forceinline__ void cp16(uint32_t d, const void* g) {
    asm volatile("cp.async.cg.shared.global [%0], [%1], 16;" :: "r"(d), "l"(g) : "memory");
}
#define CP_COMMIT() asm volatile("cp.async.commit_group;" ::: "memory")
#define CP_WAIT0()  asm volatile("cp.async.wait_group 0;" ::: "memory")
#define CP_WAIT1()  asm volatile("cp.async.wait_group 1;" ::: "memory")

// ---------------------------------------------------------------------------
// Fused conversion + counter reset.
// ---------------------------------------------------------------------------
#define XB (MROWS * DMODEL / 4 / 256)   // 4096
#define WB ((N3 / 32) * (DMODEL / 32))  // 3072

__global__ __launch_bounds__(256) void conv_fused(const float* __restrict__ x,
                                                  const float* __restrict__ W) {
    const int t = threadIdx.x;
    if (blockIdx.x == 0 && t < 8) g_hp_cnt[t] = 0u;   // reset per launch/replay
    if (blockIdx.x < XB) {
        int i = blockIdx.x * 256 + t;
        float4 v = ((const float4*)x)[i];
        ((uint32_t*)g_xh)[2 * i + 0] = cvt2h(v.x, v.y);
        ((uint32_t*)g_xh)[2 * i + 1] = cvt2h(v.z, v.w);
    } else {
        __shared__ float tl[32][33];
        const int bx = blockIdx.x - XB;
        const int tx = t & 31, ty = t >> 5;             // 32 x 8
        const int n0 = (bx % (N3 / 32)) * 32;
        const int k0 = (bx / (N3 / 32)) * 32;
#pragma unroll
        for (int j = 0; j < 4; j++)
            tl[ty + j * 8][tx] = W[(size_t)(k0 + ty + j * 8) * N3 + n0 + tx];
        __syncthreads();
#pragma unroll
        for (int j = 0; j < 4; j++) {
            int n = n0 + ty + j * 8, k = k0 + tx;
            g_wh[(size_t)n * DMODEL + k] = __float2half_rn(tl[tx][ty + j * 8]);
        }
    }
}

// ---------------------------------------------------------------------------
// Fused GEMM + attention. bid < 768: GEMM role (grouped by head pair);
// bid >= 768: attention role (spin-waits on its head pair's counter).
// Shared smem plan: 110592 B both roles; 256 threads; 2 CTAs/SM.
// ---------------------------------------------------------------------------
#define GP 144
#define GSTG (2 * 128 * GP)         // 36864 per stage
#define GBOFF (128 * GP)
#define AP 144
#define KVSZ (2 * 128 * AP)         // 36864: K | V
#define VOFF (128 * AP)
#define FUSED_SMEM (3 * GSTG)       // 110592 (== 3 * KVSZ)

#define GEMM_BLOCKS 768

__global__ __launch_bounds__(256, 2) void fused_mma(const float* __restrict__ bias,
                                                    float* __restrict__ out) {
    extern __shared__ char smem[];
    const uint32_t sb = smem_u32(smem);
    const int t = threadIdx.x;
    const int wid = t >> 5, lid = t & 31;
    const int sub = lid >> 3, r8 = lid & 7;
    const uint32_t lane_off =
        (uint32_t)((r8 + ((sub & 1) << 3)) * GP + ((sub >> 1) << 4));

    if (blockIdx.x < GEMM_BLOCKS) {
        // =================== GEMM role ===================
        const int bid = blockIdx.x;
        const int hp = bid / 96, r = bid % 96;
        const int part = r >> 5, m = r & 31;
        const int n0 = part * 1024 + hp * 128;
        const int m0 = m * 128;
        const int wm = wid >> 2, wn = wid & 3;

        const __half* gp_[8];
        uint32_t sp_[8];
#pragma unroll
        for (int it = 0; it < 8; it++) {
            int idx = t + it * 256;
            int mat = idx >> 10, w = idx & 1023;
            int row = w >> 3, c16 = w & 7;
            const __half* base;
            int grow;
            if (mat == 0) { base = g_xh; grow = m0 + row; }
            else          { base = g_wh; grow = n0 + row; }
            gp_[it] = base + (size_t)grow * DMODEL + c16 * 8;
            sp_[it] = sb + (uint32_t)(mat * GBOFF + row * GP + c16 * 16);
        }

#pragma unroll
        for (int s = 0; s < 2; s++) {
#pragma unroll
            for (int it = 0; it < 8; it++) cp16(sp_[it] + s * GSTG, gp_[it] + s * 64);
            CP_COMMIT();
        }

        float acc[4][4][4] = {};
        const int NCH = DMODEL / 64;   // 16
        int cur = 0;

        for (int ch = 0; ch < NCH; ch++) {
            if (ch == NCH - 1) { CP_WAIT0(); } else { CP_WAIT1(); }
            __syncthreads();
            const uint32_t sA = sb + (uint32_t)(cur * GSTG);
            const uint32_t sB = sA + GBOFF;

#pragma unroll
            for (int ks = 0; ks < 4; ks++) {
                const uint32_t kso = ks * 32;
                uint32_t bw[2][4];
#pragma unroll
                for (int np = 0; np < 2; np++) {
                    uint32_t baddr = (uint32_t)((wn * 32 + np * 16) * GP) + kso + lane_off;
                    ldmx4(bw[np], sB + baddr);
                }
#pragma unroll
                for (int mt = 0; mt < 4; mt++) {
                    uint32_t aaddr = (uint32_t)((wm * 64 + mt * 16) * GP) + kso + lane_off;
                    uint32_t ah[4];
                    ldmx4(ah, sA + aaddr);
#pragma unroll
                    for (int nt = 0; nt < 4; nt++) {
                        const int np = nt >> 1, o = nt & 1;
                        mma_f16(acc[mt][nt], ah, bw[np][o], bw[np][2 + o]);
                    }
                }
            }
            if (ch + 2 < NCH) {
                const int ko = (ch + 2) * 64;
                const int nb = (cur + 2 >= 3) ? cur - 1 : cur + 2;
                const uint32_t wo = (uint32_t)(nb * GSTG);
#pragma unroll
                for (int it = 0; it < 8; it++) cp16(sp_[it] + wo, gp_[it] + ko);
                CP_COMMIT();
            }
            cur = (cur == 2) ? 0 : cur + 1;
        }

        const int gid = lid >> 2, tg = lid & 3;
        __half* p_ = (part == 0) ? g_qh : (part == 1) ? g_kh : g_vh;

#pragma unroll
        for (int nt = 0; nt < 4; nt++) {
            const int col = n0 + wn * 32 + nt * 8 + tg * 2;
            const float2 bv = *(const float2*)&bias[col];
            const int h = (col >> 6) & 15, dh0 = col & 63;
#pragma unroll
            for (int mt = 0; mt < 4; mt++) {
                const int row0 = m0 + wm * 64 + mt * 16 + gid;
#pragma unroll
                for (int half = 0; half < 2; half++) {
                    const int row = row0 + half * 8;
                    const int bb = row >> 11, s = row & 2047;
                    const size_t idx =
                        ((size_t)(bb * NHEADS + h) * SEQ + s) * DHEAD + dh0;
                    *(uint32_t*)(p_ + idx) =
                        cvt2h(acc[mt][nt][2 * half + 0] + bv.x,
                              acc[mt][nt][2 * half + 1] + bv.y);
                }
            }
        }

        __threadfence();
        __syncthreads();
        if (t == 0) atomicAdd(&g_hp_cnt[hp], 1u);
    } else {
        // =================== attention role ===================
        const int a  = blockIdx.x - GEMM_BLOCKS;
        const int hp = a >> 6, rr = a & 63;
        const int h  = hp * 2 + (rr & 1);
        const int bb = (rr >> 1) & 1;
        const int q0 = (rr >> 2) * 128;

        // wait for this head pair's Q, K, V to be fully written (96 blocks)
        if (t == 0) {
            while (atomicAdd(&g_hp_cnt[hp], 0u) < 96u) __nanosleep(256);
        }
        __syncthreads();
        __threadfence();

        const int w = wid;
        const int gid = lid >> 2, tg = lid & 3;
        const size_t base = (size_t)(bb * NHEADS + h) * SEQ * DHEAD;
        const int row = t >> 3, c16 = t & 7;

#define ISSUE_KV(k0_, kvb_) do {                                               \
        size_t g_ = base + (size_t)((k0_) + row) * DHEAD + c16 * 8;            \
        uint32_t d_ = sb + (uint32_t)(kvb_) + (uint32_t)(row * AP + c16 * 16); \
        _Pragma("unroll")                                                      \
        for (int ii = 0; ii < 4; ii++) {                                       \
            cp16(d_ + 0,    g_kh + g_);                                        \
            cp16(d_ + VOFF, g_vh + g_);                                        \
            g_ += 32 * DHEAD; d_ += 32 * AP;                                   \
        }                                                                      \
    } while (0)

#pragma unroll
        for (int i = 0; i < 4; i++) {
            const int qr = row + 32 * i;
            const size_t g = base + (size_t)(q0 + qr) * DHEAD + c16 * 8;
            cp16(sb + (uint32_t)(qr * AP + c16 * 16), g_qh + g);
        }
        CP_COMMIT();
        CP_WAIT0();
        __syncthreads();

        uint32_t qf[4][4];
#pragma unroll
        for (int kc = 0; kc < 4; kc++)
            ldmx4(qf[kc], sb + (uint32_t)(w * 16 * AP) + kc * 32 + lane_off);
        __syncthreads();

        ISSUE_KV(0, 0);
        CP_COMMIT();
        ISSUE_KV(128, KVSZ);
        CP_COMMIT();

        float oacc[8][4] = {};
        float l0 = 0.f, l1 = 0.f;
        const float SL2E = 0.125f * 1.4426950408889634f;
        const float NCM  = -6.0f * 1.4426950408889634f;

        const int NT = SEQ / 128;   // 16
        int cur = 0;
        for (int kt = 0; kt < NT; kt++) {
            if (kt == NT - 1) { CP_WAIT0(); } else { CP_WAIT1(); }
            __syncthreads();
            const uint32_t kvb = sb + (uint32_t)(cur * KVSZ);

#pragma unroll
            for (int half = 0; half < 2; half++) {
                const uint32_t kbase = kvb + (uint32_t)(half * 64 * AP);
                const uint32_t vbase = kvb + VOFF + (uint32_t)(half * 64 * AP);

                float sacc[8][4] = {};
#pragma unroll
                for (int kc = 0; kc < 4; kc++) {
#pragma unroll
                    for (int np = 0; np < 4; np++) {
                        uint32_t kh4[4];
                        ldmx4(kh4, kbase + (uint32_t)(np * 16 * AP) + kc * 32 + lane_off);
#pragma unroll
                        for (int o = 0; o < 2; o++)
                            mma_f16(sacc[2 * np + o], qf[kc], kh4[o], kh4[2 + o]);
                    }
                }

#pragma unroll
                for (int kc = 0; kc < 4; kc++) {
                    const int j0 = 2 * kc, j1 = 2 * kc + 1;
                    sacc[j0][0] = ex2(fmaf(sacc[j0][0], SL2E, NCM));
                    sacc[j0][1] = ex2(fmaf(sacc[j0][1], SL2E, NCM));
                    sacc[j0][2] = ex2(fmaf(sacc[j0][2], SL2E, NCM));
                    sacc[j0][3] = ex2(fmaf(sacc[j0][3], SL2E, NCM));
                    sacc[j1][0] = ex2(fmaf(sacc[j1][0], SL2E, NCM));
                    sacc[j1][1] = ex2(fmaf(sacc[j1][1], SL2E, NCM));
                    sacc[j1][2] = ex2(fmaf(sacc[j1][2], SL2E, NCM));
                    sacc[j1][3] = ex2(fmaf(sacc[j1][3], SL2E, NCM));
                    l0 += sacc[j0][0] + sacc[j0][1] + sacc[j1][0] + sacc[j1][1];
                    l1 += sacc[j0][2] + sacc[j0][3] + sacc[j1][2] + sacc[j1][3];
                    uint32_t pah[4];
                    pah[0] = cvt2h(sacc[j0][0], sacc[j0][1]);
                    pah[1] = cvt2h(sacc[j0][2], sacc[j0][3]);
                    pah[2] = cvt2h(sacc[j1][0], sacc[j1][1]);
                    pah[3] = cvt2h(sacc[j1][2], sacc[j1][3]);
#pragma unroll
                    for (int np = 0; np < 4; np++) {
                        uint32_t vh4[4];
                        ldmx4t(vh4, vbase + (uint32_t)((kc * 16) * AP) + np * 32 + lane_off);
#pragma unroll
                        for (int o = 0; o < 2; o++)
                            mma_f16(oacc[2 * np + o], pah, vh4[2 * o], vh4[2 * o + 1]);
                    }
                }
            }

            if (kt + 2 < NT) {
                const int nb = (cur + 2 >= 3) ? cur - 1 : cur + 2;
                ISSUE_KV((kt + 2) * 128, nb * KVSZ);
                CP_COMMIT();
            }
            cur = (cur == 2) ? 0 : cur + 1;
        }

        l0 += __shfl_xor_sync(0xffffffffu, l0, 1);
        l0 += __shfl_xor_sync(0xffffffffu, l0, 2);
        l1 += __shfl_xor_sync(0xffffffffu, l1, 1);
        l1 += __shfl_xor_sync(0xffffffffu, l1, 2);
        const float inv0 = 1.0f / l0, inv1 = 1.0f / l1;
        const int qa = q0 + w * 16 + gid;
        const int qb = qa + 8;
#pragma unroll
        for (int j = 0; j < 8; j++) {
            const int col = h * DHEAD + 8 * j + 2 * tg;
            float2 v0 = {oacc[j][0] * inv0, oacc[j][1] * inv0};
            float2 v1 = {oacc[j][2] * inv1, oacc[j][3] * inv1};
            *(float2*)(out + ((size_t)bb * SEQ + qa) * DMODEL + col) = v0;
            *(float2*)(out + ((size_t)bb * SEQ + qb) * DMODEL + col) = v1;
        }
    }
}

extern "C" void kernel_launch(void* const* d_in, const int* in_sizes, int n_in,
                              void* d_out, int out_size) {
    const float* x    = (const float*)d_in[0];
    const float* W    = (const float*)d_in[1];
    const float* bias = (const float*)d_in[2];
    float* out = (float*)d_out;

    conv_fused<<<XB + WB, 256>>>(x, W);

    (void)cudaFuncSetAttribute(fused_mma,
                               cudaFuncAttributeMaxDynamicSharedMemorySize, FUSED_SMEM);
    fused_mma<<<GEMM_BLOCKS + 512, 256, FUSED_SMEM>>>(bias, out);
}